// round 3
// baseline (speedup 1.0000x reference)
#include <cuda_runtime.h>

// AlignBlock on sm_103a, round 3:
//  - chanmix2 kept as the clean f32x2 (FFMA2) experiment
//  - corr/align reverted to scalar float4 with better register blocking
//  - conv+softmax smem-tiled rewrite kept
// Shapes: B=2, C=H=64, T=512, F=64, DMAX=32. All fp32.

#define Bn 2
#define Cn 64
#define Hn 64
#define Tn 512
#define Fn 64
#define Dn 32

typedef unsigned long long u64;

__device__ __forceinline__ u64 pack2(float lo, float hi) {
    u64 r; asm("mov.b64 %0,{%1,%2};" : "=l"(r) : "f"(lo), "f"(hi)); return r;
}
__device__ __forceinline__ u64 bcast2(float x) {
    u64 r; asm("mov.b64 %0,{%1,%1};" : "=l"(r) : "f"(x)); return r;
}
__device__ __forceinline__ void ffma2(u64& d, u64 a, u64 b) {
    asm("fma.rn.f32x2 %0,%1,%2,%0;" : "+l"(d) : "l"(a), "l"(b));
}
__device__ __forceinline__ float2 unpack2(u64 v) {
    float lo, hi; asm("mov.b64 {%0,%1},%2;" : "=f"(lo), "=f"(hi) : "l"(v));
    return make_float2(lo, hi);
}

// Scratch
__device__ float g_Q[Bn * Hn * Tn * Fn];
__device__ float g_K[Bn * Hn * Tn * Fn];
__device__ float g_V[Bn * Hn * Tn * Dn];
__device__ float g_A[Bn * Tn * Dn];

// ---------------------------------------------------------------------------
// Kernel 1: channel mix for Q AND K in one launch (f32x2 FFMA experiment).
// out[b,h,t,f] = sum_c w[h,c] * x[b,c,t,f] + bias[h]
// grid = 2*B*(T/2) = 1024 blocks, 256 threads. Thread tile: 4h x 8f.
// ---------------------------------------------------------------------------
__global__ void __launch_bounds__(256) k_chanmix2(const float* __restrict__ xm,
                                                  const float* __restrict__ wm,
                                                  const float* __restrict__ bm,
                                                  const float* __restrict__ xr,
                                                  const float* __restrict__ wr,
                                                  const float* __restrict__ br) {
    const int tid = threadIdx.x;
    const int which = blockIdx.x >> 9;
    const int rem = blockIdx.x & 511;
    const int b = rem >> 8;
    const int t0 = (rem & 255) * 2;

    const float* x    = which ? xr : xm;
    const float* w    = which ? wr : wm;
    const float* bias = which ? br : bm;
    float* out        = which ? g_K : g_Q;

    __shared__ float xs[2][64][64];   // [ti][c][f]
    __shared__ float ws[64][64];      // [h][c]

#pragma unroll
    for (int it = 0; it < 16; it++) {
        int idx = tid + it * 256;
        ws[idx >> 6][idx & 63] = w[idx];
    }
#pragma unroll
    for (int it = 0; it < 8; it++) {
        int idx = tid + it * 256;              // float4 index 0..2047
        int f4 = (idx & 15) * 4;
        int c  = (idx >> 4) & 63;
        int ti = idx >> 10;
        *(float4*)&xs[ti][c][f4] =
            *(const float4*)&x[((b * 64 + c) * 512 + t0 + ti) * 64 + f4];
    }
    __syncthreads();

    const int ti = tid >> 7;
    const int l  = tid & 127;
    const int h0 = (l >> 3) * 4;
    const int f0 = (l & 7) * 8;

    u64 acc[4][4];
#pragma unroll
    for (int a = 0; a < 4; a++)
#pragma unroll
        for (int p = 0; p < 4; p++) acc[a][p] = 0ULL;

#pragma unroll 4
    for (int c = 0; c < 64; c++) {
        float4 x0 = *(const float4*)&xs[ti][c][f0];
        float4 x1 = *(const float4*)&xs[ti][c][f0 + 4];
        u64 xp0 = pack2(x0.x, x0.y);
        u64 xp1 = pack2(x0.z, x0.w);
        u64 xp2 = pack2(x1.x, x1.y);
        u64 xp3 = pack2(x1.z, x1.w);
#pragma unroll
        for (int a = 0; a < 4; a++) {
            u64 wb = bcast2(ws[h0 + a][c]);
            ffma2(acc[a][0], wb, xp0);
            ffma2(acc[a][1], wb, xp1);
            ffma2(acc[a][2], wb, xp2);
            ffma2(acc[a][3], wb, xp3);
        }
    }

#pragma unroll
    for (int a = 0; a < 4; a++) {
        float bb = __ldg(&bias[h0 + a]);
        float2 v0 = unpack2(acc[a][0]), v1 = unpack2(acc[a][1]);
        float2 v2 = unpack2(acc[a][2]), v3 = unpack2(acc[a][3]);
        float4 r0 = make_float4(v0.x + bb, v0.y + bb, v1.x + bb, v1.y + bb);
        float4 r1 = make_float4(v2.x + bb, v2.y + bb, v3.x + bb, v3.y + bb);
        float* og = &out[((b * 64 + h0 + a) * 512 + t0 + ti) * 64 + f0];
        *(float4*)og = r0;
        *(float4*)(og + 4) = r1;
    }
}

// ---------------------------------------------------------------------------
// Kernel 2: banded correlation, scalar float4, 4t x 8d thread tiles.
// V[b,h,t,d] = (1/8) * sum_f Q[b,h,t,f] * K[b,h,t-31+d,f]
// grid = B*H*(T/64) = 1024 blocks, 64 threads.
// ---------------------------------------------------------------------------
__global__ void __launch_bounds__(64) k_corr() {
    const int tid = threadIdx.x;
    const int t0 = (blockIdx.x & 7) * 64;
    const int h  = (blockIdx.x >> 3) & 63;
    const int b  = blockIdx.x >> 9;

    __shared__ float Qs[64][68];    // [f][i]
    __shared__ float Ks[64][96];    // [f][r], r = t_global - (t0-31), 0..94

    const float* qg = g_Q + ((b * 64 + h) * 512 + t0) * 64;
    const float* kg = g_K + ((b * 64 + h) * 512) * 64;

    for (int idx = tid; idx < 64 * 64; idx += 64) {
        int i = idx >> 6, f = idx & 63;
        Qs[f][i] = qg[i * 64 + f];
    }
    for (int idx = tid; idx < 95 * 64; idx += 64) {
        int r = idx >> 6, f = idx & 63;
        int tr = t0 - 31 + r;
        Ks[f][r] = (tr >= 0) ? kg[tr * 64 + f] : 0.0f;
    }
    __syncthreads();

    const int d0 = (tid & 3) * 8;    // 0,8,16,24
    const int i0 = (tid >> 2) * 4;   // 0..60

    float acc[4][8];
#pragma unroll
    for (int a = 0; a < 4; a++)
#pragma unroll
        for (int e = 0; e < 8; e++) acc[a][e] = 0.f;

#pragma unroll 4
    for (int f = 0; f < 64; f++) {
        float4 q4 = *(const float4*)&Qs[f][i0];
        float4 k0 = *(const float4*)&Ks[f][i0 + d0];
        float4 k1 = *(const float4*)&Ks[f][i0 + d0 + 4];
        float4 k2 = *(const float4*)&Ks[f][i0 + d0 + 8];   // kk[11] unused
        float qq[4] = {q4.x, q4.y, q4.z, q4.w};
        float kk[12] = {k0.x, k0.y, k0.z, k0.w, k1.x, k1.y, k1.z, k1.w,
                        k2.x, k2.y, k2.z, k2.w};
#pragma unroll
        for (int a = 0; a < 4; a++)
#pragma unroll
            for (int e = 0; e < 8; e++)
                acc[a][e] += qq[a] * kk[a + e];   // K row = (i0+a)+(d0+e)
    }

    float* vg = g_V + ((b * 64 + h) * 512 + t0) * 32;
#pragma unroll
    for (int a = 0; a < 4; a++) {
        float4 r0 = make_float4(acc[a][0] * 0.125f, acc[a][1] * 0.125f,
                                acc[a][2] * 0.125f, acc[a][3] * 0.125f);
        float4 r1 = make_float4(acc[a][4] * 0.125f, acc[a][5] * 0.125f,
                                acc[a][6] * 0.125f, acc[a][7] * 0.125f);
        *(float4*)&vg[(i0 + a) * 32 + d0] = r0;
        *(float4*)&vg[(i0 + a) * 32 + d0 + 4] = r1;
    }
}

// ---------------------------------------------------------------------------
// Kernel 3: (5,3) conv over (T,dmax) reducing H->1, + softmax over dmax.
// (conv bias dropped: uniform shift is softmax-invariant)
// grid = B*(T/8) = 128 blocks, 128 threads.
// ---------------------------------------------------------------------------
__global__ void __launch_bounds__(128) k_convsoftmax(const float* __restrict__ wconv) {
    const int tid = threadIdx.x;
    const int b  = blockIdx.x >> 6;
    const int t0 = (blockIdx.x & 63) * 8;

    __shared__ float Vs[16][12][34];  // [h_local][row r: t0-4+r][1+d], pads 0,33
    __shared__ float wcs[64][16];
    __shared__ float red[8][33];

    for (int idx = tid; idx < 960; idx += 128)
        wcs[idx / 15][idx % 15] = wconv[idx];
    for (int idx = tid; idx < 16 * 12; idx += 128) {
        Vs[idx / 12][idx % 12][0]  = 0.0f;
        Vs[idx / 12][idx % 12][33] = 0.0f;
    }

    const int tl = tid >> 4;        // 0..7
    const int d  = (tid & 15) * 2;  // even

    float accA0 = 0.f, accA1 = 0.f, accB0 = 0.f, accB1 = 0.f;

    for (int hc = 0; hc < 4; hc++) {
        __syncthreads();
        for (int g = tid; g < 1536; g += 128) {
            int dq = g & 7;
            int hr = g >> 3;
            int r  = hr % 12;
            int hl = hr / 12;
            int tt = t0 - 4 + r;
            float4 v = make_float4(0.f, 0.f, 0.f, 0.f);
            if (tt >= 0)
                v = *(const float4*)&g_V[((b * 64 + hc * 16 + hl) * 512 + tt) * 32 + dq * 4];
            Vs[hl][r][1 + dq * 4 + 0] = v.x;
            Vs[hl][r][1 + dq * 4 + 1] = v.y;
            Vs[hl][r][1 + dq * 4 + 2] = v.z;
            Vs[hl][r][1 + dq * 4 + 3] = v.w;
        }
        __syncthreads();

#pragma unroll 2
        for (int hl = 0; hl < 16; hl++) {
            int hh = hc * 16 + hl;
            float wreg[16];
#pragma unroll
            for (int k4 = 0; k4 < 4; k4++) {
                float4 wv = *(const float4*)&wcs[hh][k4 * 4];
                wreg[k4 * 4 + 0] = wv.x; wreg[k4 * 4 + 1] = wv.y;
                wreg[k4 * 4 + 2] = wv.z; wreg[k4 * 4 + 3] = wv.w;
            }
#pragma unroll
            for (int i = 0; i < 5; i++) {
                float2 u = *(const float2*)&Vs[hl][tl + i][d];
                float2 v = *(const float2*)&Vs[hl][tl + i][d + 2];
                float w0 = wreg[i * 3], w1 = wreg[i * 3 + 1], w2 = wreg[i * 3 + 2];
                if (i & 1) {
                    accB0 += u.x * w0 + u.y * w1 + v.x * w2;
                    accB1 += u.y * w0 + v.x * w1 + v.y * w2;
                } else {
                    accA0 += u.x * w0 + u.y * w1 + v.x * w2;
                    accA1 += u.y * w0 + v.x * w1 + v.y * w2;
                }
            }
        }
    }

    red[tl][d]     = accA0 + accB0;
    red[tl][d + 1] = accA1 + accB1;
    __syncthreads();

    const int wid = tid >> 5, lane = tid & 31;
#pragma unroll
    for (int rr = 0; rr < 2; rr++) {
        int row = wid * 2 + rr;
        float v = red[row][lane];
        float mx = v;
#pragma unroll
        for (int o = 16; o > 0; o >>= 1)
            mx = fmaxf(mx, __shfl_xor_sync(0xffffffffu, mx, o));
        float e = __expf(v - mx);
        float s = e;
#pragma unroll
        for (int o = 16; o > 0; o >>= 1)
            s += __shfl_xor_sync(0xffffffffu, s, o);
        g_A[(b * 512 + t0 + row) * 32 + lane] = e / s;
    }
}

// ---------------------------------------------------------------------------
// Kernel 4: aligned[b,c,t,f] = sum_d A[b,t,d] * x_ref[b,c,t-31+d,f]
// grid = B*C*(T/64) = 1024 blocks, 256 threads. Thread tile: 4t x 4f,
// rolling 7-row X register window (4 new LDS.128 per d0 step).
// ---------------------------------------------------------------------------
__global__ void __launch_bounds__(256) k_align(const float* __restrict__ xref,
                                               float* __restrict__ out) {
    const int tid = threadIdx.x;
    const int t0 = (blockIdx.x & 7) * 64;
    const int c  = (blockIdx.x >> 3) & 63;
    const int b  = blockIdx.x >> 9;

    __shared__ float As[64][36];    // [i][d]
    __shared__ float Xs[95][68];    // [r][f], r = t_global - (t0-31)

    const float* ag = g_A + (b * 512 + t0) * 32;
    const float* xg = xref + ((b * 64 + c) * 512) * 64;

    for (int idx = tid; idx < 64 * 8; idx += 256) {          // A: 512 float4
        int i = idx >> 3, dq = idx & 7;
        *(float4*)&As[i][dq * 4] = *(const float4*)&ag[i * 32 + dq * 4];
    }
    for (int idx = tid; idx < 95 * 16; idx += 256) {         // X: 1520 float4
        int r = idx >> 4, fq = idx & 15;
        int tr = t0 - 31 + r;
        float4 v = make_float4(0.f, 0.f, 0.f, 0.f);
        if (tr >= 0) v = *(const float4*)&xg[tr * 64 + fq * 4];
        *(float4*)&Xs[r][fq * 4] = v;
    }
    __syncthreads();

    const int f0 = (tid & 15) * 4;   // 0..60
    const int i0 = (tid >> 4) * 4;   // 0..60

    float4 acc[4];
#pragma unroll
    for (int a = 0; a < 4; a++) acc[a] = make_float4(0.f, 0.f, 0.f, 0.f);

    float4 xv[7];
#pragma unroll
    for (int k = 0; k < 7; k++)
        xv[k] = *(const float4*)&Xs[i0 + k][f0];

#pragma unroll
    for (int d0 = 0; d0 < 32; d0 += 4) {
        float4 av[4];
#pragma unroll
        for (int a = 0; a < 4; a++) av[a] = *(const float4*)&As[i0 + a][d0];
#pragma unroll
        for (int a = 0; a < 4; a++) {
            float aa[4] = {av[a].x, av[a].y, av[a].z, av[a].w};
#pragma unroll
            for (int dd = 0; dd < 4; dd++) {
                float4 x4 = xv[a + dd];     // row (i0+a)+(d0+dd) relative base
                acc[a].x += aa[dd] * x4.x;
                acc[a].y += aa[dd] * x4.y;
                acc[a].z += aa[dd] * x4.z;
                acc[a].w += aa[dd] * x4.w;
            }
        }
        if (d0 < 28) {
            xv[0] = xv[4]; xv[1] = xv[5]; xv[2] = xv[6];
#pragma unroll
            for (int k = 3; k < 7; k++)
                xv[k] = *(const float4*)&Xs[i0 + d0 + 4 + k][f0];
        }
    }

    float* og = out + ((b * 64 + c) * 512 + t0) * 64;
#pragma unroll
    for (int a = 0; a < 4; a++)
        *(float4*)&og[(i0 + a) * 64 + f0] = acc[a];
}

// ---------------------------------------------------------------------------
extern "C" void kernel_launch(void* const* d_in, const int* in_sizes, int n_in,
                              void* d_out, int out_size) {
    (void)in_sizes; (void)n_in; (void)out_size;
    const float* x_mic  = (const float*)d_in[0];
    const float* x_ref  = (const float*)d_in[1];
    const float* w_mic  = (const float*)d_in[2];
    const float* b_mic  = (const float*)d_in[3];
    const float* w_ref  = (const float*)d_in[4];
    const float* b_ref  = (const float*)d_in[5];
    const float* w_conv = (const float*)d_in[6];
    float* out = (float*)d_out;

    k_chanmix2<<<2 * Bn * (Tn / 2), 256>>>(x_mic, w_mic, b_mic, x_ref, w_ref, b_ref);
    k_corr<<<Bn * Hn * (Tn / 64), 64>>>();
    k_convsoftmax<<<Bn * (Tn / 8), 128>>>(w_conv);
    k_align<<<Bn * Cn * (Tn / 64), 256>>>(x_ref, out);
}

// round 5
// speedup vs baseline: 1.3344x; 1.3344x over previous
#include <cuda_runtime.h>
#include <cuda_bf16.h>
#include <cstdint>

// AlignBlock on sm_103a (ptxas target sm_103 -> no tcgen05; use mma.sync HMMA).
// Round 5:
//  - chanmix via mma.sync m16n8k16 bf16 with 3-term hi/lo split (fp32-accurate)
//  - corr: r1 scalar version; conv+softmax: r2 rewrite; align: r3 version
// Shapes: B=2, C=H=64, T=512, F=64, DMAX=32.

#define Bn 2
#define Cn 64
#define Hn 64
#define Tn 512
#define Fn 64
#define Dn 32

__device__ float g_Q[Bn * Hn * Tn * Fn];
__device__ float g_K[Bn * Hn * Tn * Fn];
__device__ float g_V[Bn * Hn * Tn * Dn];
__device__ float g_A[Bn * Tn * Dn];

// ---------------------------------------------------------------------------
// Kernel 1: channel mix as GEMM on tensor cores (mma.sync, bf16 split).
// out[h, n] = sum_c w[h,c] * x[c,n] + bias[h],  n = t*64+f (32768 per b).
// grid = which(2) x b(2) x ntile(256) = 1024 CTAs, 256 threads.
// CTA tile: 64h x 128n, K = 64. Warp tile m32 x n32.
// smem rows padded to 72 bf16 (144B) -> all fragment LDS.32 conflict-free.
// ---------------------------------------------------------------------------
#define MMA16816(d, a, b)                                                     \
    asm volatile(                                                             \
        "mma.sync.aligned.m16n8k16.row.col.f32.bf16.bf16.f32 "                \
        "{%0,%1,%2,%3}, {%4,%5,%6,%7}, {%8,%9}, {%0,%1,%2,%3};"               \
        : "+f"((d)[0]), "+f"((d)[1]), "+f"((d)[2]), "+f"((d)[3])              \
        : "r"((a)[0]), "r"((a)[1]), "r"((a)[2]), "r"((a)[3]),                 \
          "r"((b)[0]), "r"((b)[1]))

#define WPAD 72
#define CM_SMEM ((64 * WPAD * 2 + 128 * WPAD * 2) * 2)   // 55296 bytes

__global__ void __launch_bounds__(256) k_chanmma(const float* __restrict__ xm,
                                                 const float* __restrict__ wm,
                                                 const float* __restrict__ bm,
                                                 const float* __restrict__ xr,
                                                 const float* __restrict__ wr,
                                                 const float* __restrict__ br) {
    extern __shared__ __nv_bfloat16 sm[];
    __nv_bfloat16* ws_hi = sm;                    // [64][WPAD]
    __nv_bfloat16* ws_lo = ws_hi + 64 * WPAD;
    __nv_bfloat16* xs_hi = ws_lo + 64 * WPAD;     // [128][WPAD]
    __nv_bfloat16* xs_lo = xs_hi + 128 * WPAD;

    const int tid = threadIdx.x;
    const int tile  = blockIdx.x & 255;
    const int b     = (blockIdx.x >> 8) & 1;
    const int which = blockIdx.x >> 9;
    const int n0    = tile * 128;

    const float* x    = which ? xr : xm;
    const float* w    = which ? wr : wm;
    const float* bias = which ? br : bm;
    float* outp = (which ? g_K : g_Q) + b * 64 * 32768;

    // ---- w fill: 4096 elems (1024 float4), hi/lo split
#pragma unroll
    for (int it = 0; it < 4; it++) {
        int idx = tid + it * 256;                 // 0..1023
        int h = idx >> 4, c0 = (idx & 15) * 4;
        float4 wv = *(const float4*)&w[h * 64 + c0];
        float vv[4] = {wv.x, wv.y, wv.z, wv.w};
#pragma unroll
        for (int j = 0; j < 4; j += 2) {
            __nv_bfloat16 h0 = __float2bfloat16(vv[j]);
            __nv_bfloat16 h1 = __float2bfloat16(vv[j + 1]);
            __nv_bfloat16 l0 = __float2bfloat16(vv[j] - __bfloat162float(h0));
            __nv_bfloat16 l1 = __float2bfloat16(vv[j + 1] - __bfloat162float(h1));
            __nv_bfloat162 hh; hh.x = h0; hh.y = h1;
            __nv_bfloat162 ll; ll.x = l0; ll.y = l1;
            *(__nv_bfloat162*)&ws_hi[h * WPAD + c0 + j] = hh;
            *(__nv_bfloat162*)&ws_lo[h * WPAD + c0 + j] = ll;
        }
    }

    // ---- x fill: xs[n][c] = x[c][n0+n]; 8192 elems (2048 float4)
#pragma unroll
    for (int it = 0; it < 8; it++) {
        int idx = tid + it * 256;                 // 0..2047
        int c = idx >> 5;
        int n = (idx & 31) * 4;
        float4 v = *(const float4*)&x[(b * 64 + c) * 32768 + n0 + n];
        float vv[4] = {v.x, v.y, v.z, v.w};
#pragma unroll
        for (int j = 0; j < 4; j++) {
            __nv_bfloat16 hi = __float2bfloat16(vv[j]);
            __nv_bfloat16 lo = __float2bfloat16(vv[j] - __bfloat162float(hi));
            xs_hi[(n + j) * WPAD + c] = hi;
            xs_lo[(n + j) * WPAD + c] = lo;
        }
    }
    __syncthreads();

    const int warp = tid >> 5, lane = tid & 31;
    const int group = lane >> 2, tig = lane & 3;
    const int m0  = (warp >> 2) * 32;             // 0 or 32
    const int nw0 = (warp & 3) * 32;              // 0,32,64,96

    float acc[2][4][4];
#pragma unroll
    for (int mt = 0; mt < 2; mt++)
#pragma unroll
        for (int nt = 0; nt < 4; nt++)
#pragma unroll
            for (int e = 0; e < 4; e++) acc[mt][nt][e] = 0.f;

#pragma unroll
    for (int k0 = 0; k0 < 64; k0 += 16) {
        uint32_t ah[2][4], al[2][4];
#pragma unroll
        for (int mt = 0; mt < 2; mt++) {
            int r0 = m0 + mt * 16 + group;
            const __nv_bfloat16* ph = &ws_hi[r0 * WPAD + k0 + 2 * tig];
            const __nv_bfloat16* pl = &ws_lo[r0 * WPAD + k0 + 2 * tig];
            ah[mt][0] = *(const uint32_t*)ph;
            ah[mt][1] = *(const uint32_t*)(ph + 8 * WPAD);
            ah[mt][2] = *(const uint32_t*)(ph + 8);
            ah[mt][3] = *(const uint32_t*)(ph + 8 * WPAD + 8);
            al[mt][0] = *(const uint32_t*)pl;
            al[mt][1] = *(const uint32_t*)(pl + 8 * WPAD);
            al[mt][2] = *(const uint32_t*)(pl + 8);
            al[mt][3] = *(const uint32_t*)(pl + 8 * WPAD + 8);
        }
        uint32_t bh[4][2], bl[4][2];
#pragma unroll
        for (int nt = 0; nt < 4; nt++) {
            int nn = nw0 + nt * 8 + group;
            const __nv_bfloat16* ph = &xs_hi[nn * WPAD + k0 + 2 * tig];
            const __nv_bfloat16* pl = &xs_lo[nn * WPAD + k0 + 2 * tig];
            bh[nt][0] = *(const uint32_t*)ph;
            bh[nt][1] = *(const uint32_t*)(ph + 8);
            bl[nt][0] = *(const uint32_t*)pl;
            bl[nt][1] = *(const uint32_t*)(pl + 8);
        }
#pragma unroll
        for (int mt = 0; mt < 2; mt++)
#pragma unroll
            for (int nt = 0; nt < 4; nt++) {
                MMA16816(acc[mt][nt], ah[mt], bh[nt]);
                MMA16816(acc[mt][nt], ah[mt], bl[nt]);
                MMA16816(acc[mt][nt], al[mt], bh[nt]);
            }
    }

    // ---- epilogue: direct STG.64 per (row, n-pair), + bias
#pragma unroll
    for (int mt = 0; mt < 2; mt++) {
        int r0 = m0 + mt * 16 + group;
        float b0 = __ldg(&bias[r0]);
        float b1 = __ldg(&bias[r0 + 8]);
#pragma unroll
        for (int nt = 0; nt < 4; nt++) {
            int nn = n0 + nw0 + nt * 8 + 2 * tig;
            float2 v0 = make_float2(acc[mt][nt][0] + b0, acc[mt][nt][1] + b0);
            float2 v1 = make_float2(acc[mt][nt][2] + b1, acc[mt][nt][3] + b1);
            *(float2*)&outp[r0 * 32768 + nn] = v0;
            *(float2*)&outp[(r0 + 8) * 32768 + nn] = v1;
        }
    }
}

// ---------------------------------------------------------------------------
// Kernel 2: banded correlation (r1: 128 threads, 4t x 4d tiles).
// V[b,h,t,d] = (1/8) * sum_f Q[b,h,t,f] * K[b,h,t-31+d,f]
// ---------------------------------------------------------------------------
__global__ void __launch_bounds__(128) k_corr() {
    const int tid = threadIdx.x;
    const int t0 = (blockIdx.x & 7) * 64;
    const int h  = (blockIdx.x >> 3) & 63;
    const int b  = blockIdx.x >> 9;

    __shared__ float Qs[64][68];
    __shared__ float Ks[64][100];

    const float* qg = g_Q + ((b * 64 + h) * 512 + t0) * 64;
    const float* kg = g_K + ((b * 64 + h) * 512) * 64;

    for (int idx = tid; idx < 64 * 64; idx += 128) {
        int i = idx >> 6, f = idx & 63;
        Qs[f][i] = qg[i * 64 + f];
    }
    for (int idx = tid; idx < 95 * 64; idx += 128) {
        int r = idx >> 6, f = idx & 63;
        int tr = t0 - 31 + r;
        Ks[f][r] = (tr >= 0) ? kg[tr * 64 + f] : 0.0f;
    }
    __syncthreads();

    const int d0 = (tid & 7) * 4;
    const int i0 = (tid >> 3) * 4;

    float acc[4][4];
#pragma unroll
    for (int a = 0; a < 4; a++)
#pragma unroll
        for (int e = 0; e < 4; e++) acc[a][e] = 0.f;

#pragma unroll 8
    for (int f = 0; f < 64; f++) {
        float4 q4 = *(const float4*)&Qs[f][i0];
        float4 k0 = *(const float4*)&Ks[f][i0 + d0];
        float4 k1 = *(const float4*)&Ks[f][i0 + d0 + 4];
        float qq[4] = {q4.x, q4.y, q4.z, q4.w};
        float kk[8] = {k0.x, k0.y, k0.z, k0.w, k1.x, k1.y, k1.z, k1.w};
#pragma unroll
        for (int a = 0; a < 4; a++)
#pragma unroll
            for (int e = 0; e < 4; e++)
                acc[a][e] += qq[a] * kk[a + e];
    }

    float* vg = g_V + ((b * 64 + h) * 512 + t0) * 32;
#pragma unroll
    for (int a = 0; a < 4; a++) {
        float4 r = make_float4(acc[a][0] * 0.125f, acc[a][1] * 0.125f,
                               acc[a][2] * 0.125f, acc[a][3] * 0.125f);
        *(float4*)&vg[(i0 + a) * 32 + d0] = r;
    }
}

// ---------------------------------------------------------------------------
// Kernel 3: (5,3) conv over (T,dmax) reducing H->1, + softmax over dmax.
// ---------------------------------------------------------------------------
__global__ void __launch_bounds__(128) k_convsoftmax(const float* __restrict__ wconv) {
    const int tid = threadIdx.x;
    const int b  = blockIdx.x >> 6;
    const int t0 = (blockIdx.x & 63) * 8;

    __shared__ float Vs[16][12][34];
    __shared__ float wcs[64][16];
    __shared__ float red[8][33];

    for (int idx = tid; idx < 960; idx += 128)
        wcs[idx / 15][idx % 15] = wconv[idx];
    for (int idx = tid; idx < 16 * 12; idx += 128) {
        Vs[idx / 12][idx % 12][0]  = 0.0f;
        Vs[idx / 12][idx % 12][33] = 0.0f;
    }

    const int tl = tid >> 4;
    const int d  = (tid & 15) * 2;

    float accA0 = 0.f, accA1 = 0.f, accB0 = 0.f, accB1 = 0.f;

    for (int hc = 0; hc < 4; hc++) {
        __syncthreads();
        for (int g = tid; g < 1536; g += 128) {
            int dq = g & 7;
            int hr = g >> 3;
            int r  = hr % 12;
            int hl = hr / 12;
            int tt = t0 - 4 + r;
            float4 v = make_float4(0.f, 0.f, 0.f, 0.f);
            if (tt >= 0)
                v = *(const float4*)&g_V[((b * 64 + hc * 16 + hl) * 512 + tt) * 32 + dq * 4];
            Vs[hl][r][1 + dq * 4 + 0] = v.x;
            Vs[hl][r][1 + dq * 4 + 1] = v.y;
            Vs[hl][r][1 + dq * 4 + 2] = v.z;
            Vs[hl][r][1 + dq * 4 + 3] = v.w;
        }
        __syncthreads();

#pragma unroll 2
        for (int hl = 0; hl < 16; hl++) {
            int hh = hc * 16 + hl;
            float wreg[16];
#pragma unroll
            for (int k4 = 0; k4 < 4; k4++) {
                float4 wv = *(const float4*)&wcs[hh][k4 * 4];
                wreg[k4 * 4 + 0] = wv.x; wreg[k4 * 4 + 1] = wv.y;
                wreg[k4 * 4 + 2] = wv.z; wreg[k4 * 4 + 3] = wv.w;
            }
#pragma unroll
            for (int i = 0; i < 5; i++) {
                float2 u = *(const float2*)&Vs[hl][tl + i][d];
                float2 v = *(const float2*)&Vs[hl][tl + i][d + 2];
                float w0 = wreg[i * 3], w1 = wreg[i * 3 + 1], w2 = wreg[i * 3 + 2];
                if (i & 1) {
                    accB0 += u.x * w0 + u.y * w1 + v.x * w2;
                    accB1 += u.y * w0 + v.x * w1 + v.y * w2;
                } else {
                    accA0 += u.x * w0 + u.y * w1 + v.x * w2;
                    accA1 += u.y * w0 + v.x * w1 + v.y * w2;
                }
            }
        }
    }

    red[tl][d]     = accA0 + accB0;
    red[tl][d + 1] = accA1 + accB1;
    __syncthreads();

    const int wd = tid >> 5, lane = tid & 31;
#pragma unroll
    for (int rr = 0; rr < 2; rr++) {
        int row = wd * 2 + rr;
        float v = red[row][lane];
        float mx = v;
#pragma unroll
        for (int o = 16; o > 0; o >>= 1)
            mx = fmaxf(mx, __shfl_xor_sync(0xffffffffu, mx, o));
        float e = __expf(v - mx);
        float s = e;
#pragma unroll
        for (int o = 16; o > 0; o >>= 1)
            s += __shfl_xor_sync(0xffffffffu, s, o);
        g_A[(b * 512 + t0 + row) * 32 + lane] = e / s;
    }
}

// ---------------------------------------------------------------------------
// Kernel 4: aligned[b,c,t,f] = sum_d A[b,t,d] * x_ref[b,c,t-31+d,f]
// ---------------------------------------------------------------------------
__global__ void __launch_bounds__(256) k_align(const float* __restrict__ xref,
                                               float* __restrict__ out) {
    const int tid = threadIdx.x;
    const int t0 = (blockIdx.x & 7) * 64;
    const int c  = (blockIdx.x >> 3) & 63;
    const int b  = blockIdx.x >> 9;

    __shared__ float As[64][36];
    __shared__ float Xs[95][68];

    const float* ag = g_A + (b * 512 + t0) * 32;
    const float* xg = xref + ((b * 64 + c) * 512) * 64;

    for (int idx = tid; idx < 64 * 8; idx += 256) {
        int i = idx >> 3, dq = idx & 7;
        *(float4*)&As[i][dq * 4] = *(const float4*)&ag[i * 32 + dq * 4];
    }
    for (int idx = tid; idx < 95 * 16; idx += 256) {
        int r = idx >> 4, fq = idx & 15;
        int tr = t0 - 31 + r;
        float4 v = make_float4(0.f, 0.f, 0.f, 0.f);
        if (tr >= 0) v = *(const float4*)&xg[tr * 64 + fq * 4];
        *(float4*)&Xs[r][fq * 4] = v;
    }
    __syncthreads();

    const int f0 = (tid & 15) * 4;
    const int i0 = (tid >> 4) * 4;

    float4 acc[4];
#pragma unroll
    for (int a = 0; a < 4; a++) acc[a] = make_float4(0.f, 0.f, 0.f, 0.f);

    float4 xv[7];
#pragma unroll
    for (int k = 0; k < 7; k++)
        xv[k] = *(const float4*)&Xs[i0 + k][f0];

#pragma unroll
    for (int d0 = 0; d0 < 32; d0 += 4) {
        float4 av[4];
#pragma unroll
        for (int a = 0; a < 4; a++) av[a] = *(const float4*)&As[i0 + a][d0];
#pragma unroll
        for (int a = 0; a < 4; a++) {
            float aa[4] = {av[a].x, av[a].y, av[a].z, av[a].w};
#pragma unroll
            for (int dd = 0; dd < 4; dd++) {
                float4 x4 = xv[a + dd];
                acc[a].x += aa[dd] * x4.x;
                acc[a].y += aa[dd] * x4.y;
                acc[a].z += aa[dd] * x4.z;
                acc[a].w += aa[dd] * x4.w;
            }
        }
        if (d0 < 28) {
            xv[0] = xv[4]; xv[1] = xv[5]; xv[2] = xv[6];
#pragma unroll
            for (int k = 3; k < 7; k++)
                xv[k] = *(const float4*)&Xs[i0 + d0 + 4 + k][f0];
        }
    }

    float* og = out + ((b * 64 + c) * 512 + t0) * 64;
#pragma unroll
    for (int a = 0; a < 4; a++)
        *(float4*)&og[(i0 + a) * 64 + f0] = acc[a];
}

// ---------------------------------------------------------------------------
extern "C" void kernel_launch(void* const* d_in, const int* in_sizes, int n_in,
                              void* d_out, int out_size) {
    (void)in_sizes; (void)n_in; (void)out_size;
    const float* x_mic  = (const float*)d_in[0];
    const float* x_ref  = (const float*)d_in[1];
    const float* w_mic  = (const float*)d_in[2];
    const float* b_mic  = (const float*)d_in[3];
    const float* w_ref  = (const float*)d_in[4];
    const float* b_ref  = (const float*)d_in[5];
    const float* w_conv = (const float*)d_in[6];
    float* out = (float*)d_out;

    static int smem_set = 0;
    if (!smem_set) {
        cudaFuncSetAttribute(k_chanmma, cudaFuncAttributeMaxDynamicSharedMemorySize,
                             CM_SMEM);
        smem_set = 1;
    }

    k_chanmma<<<1024, 256, CM_SMEM>>>(x_mic, w_mic, b_mic, x_ref, w_ref, b_ref);
    k_corr<<<Bn * Hn * (Tn / 64), 128>>>();
    k_convsoftmax<<<Bn * (Tn / 8), 128>>>(w_conv);
    k_align<<<Bn * Cn * (Tn / 64), 256>>>(x_ref, out);
}